// round 2
// baseline (speedup 1.0000x reference)
#include <cuda_runtime.h>
#include <math.h>

#define TS   32                 // output tile (square)
#define HALO 3                  // NMS(1) + Sobel(1) + Gauss(1)
#define INS  (TS + 2*HALO)      // 38: staged image tile
#define SMS  (TS + 4)           // 36: smoothed tile
#define EDS  (TS + 2)           // 34: edge-magnitude tile
#define PITCH 40                // padded row stride (avoid bank conflicts)

__global__ __launch_bounds__(256)
void edge_detector_kernel(const float* __restrict__ img,
                          float* __restrict__ out,
                          int H, int W)
{
    __shared__ float s_in[INS][PITCH];
    __shared__ float s_sm[SMS][PITCH];
    __shared__ float s_ed[EDS][PITCH];

    const int n   = blockIdx.z;
    const int gy0 = blockIdx.y * TS - HALO;
    const int gx0 = blockIdx.x * TS - HALO;
    const int tid = threadIdx.y * 32 + threadIdx.x;

    const float* im = img + (size_t)n * H * W;

    // ---- Stage 0: load image tile + halo (zero-pad outside image = SAME conv) ----
    #pragma unroll
    for (int idx = tid; idx < INS * INS; idx += 256) {
        int r = idx / INS, c = idx - r * INS;
        int gy = gy0 + r, gx = gx0 + c;
        float v = 0.0f;
        if (gy >= 0 && gy < H && gx >= 0 && gx < W)
            v = __ldg(&im[(size_t)gy * W + gx]);
        s_in[r][c] = v;
    }
    __syncthreads();

    // ---- Stage 1: Gauss 3x3. IMPORTANT: the reference zero-pads the SMOOTHED
    // array for the Sobel SAME conv, so smoothed values at coordinates outside
    // the image must be exactly 0, not Gauss-of-zero-padded-image. ----
    #pragma unroll
    for (int idx = tid; idx < SMS * SMS; idx += 256) {
        int r = idx / SMS, c = idx - r * SMS;
        int gy = gy0 + r + 1, gx = gx0 + c + 1;   // global coord of this smoothed px
        float v = 0.0f;
        if (gy >= 0 && gy < H && gx >= 0 && gx < W) {
            float t0 = s_in[r    ][c] + 2.0f * s_in[r    ][c+1] + s_in[r    ][c+2];
            float t1 = s_in[r + 1][c] + 2.0f * s_in[r + 1][c+1] + s_in[r + 1][c+2];
            float t2 = s_in[r + 2][c] + 2.0f * s_in[r + 2][c+1] + s_in[r + 2][c+2];
            v = (t0 + 2.0f * t1 + t2) * 0.0625f;
        }
        s_sm[r][c] = v;
    }
    __syncthreads();

    // ---- Stage 2: Sobel X/Y + magnitude ----
    #pragma unroll
    for (int idx = tid; idx < EDS * EDS; idx += 256) {
        int r = idx / EDS, c = idx - r * EDS;
        float a = s_sm[r    ][c], b = s_sm[r    ][c+1], cc = s_sm[r    ][c+2];
        float d = s_sm[r + 1][c],                       f  = s_sm[r + 1][c+2];
        float g = s_sm[r + 2][c], h = s_sm[r + 2][c+1], i  = s_sm[r + 2][c+2];
        // SOBEL_X = [[-1,0,1],[-2,0,2],[-1,0,1]]
        float gx = (cc - a) + 2.0f * (f - d) + (i - g);
        // SOBEL_Y = SOBEL_X^T = [[-1,-2,-1],[0,0,0],[1,2,1]]
        float gy = (g - a) + 2.0f * (h - b) + (i - cc);
        s_ed[r][c] = sqrtf(gx * gx + gy * gy);
    }
    __syncthreads();

    // ---- Stage 3: NMS over 8 neighbors; borders pass through untouched ----
    const size_t out_base = (size_t)n * H * W;
    #pragma unroll
    for (int k = 0; k < 4; k++) {
        int ty = threadIdx.y + k * 8;
        int tx = threadIdx.x;
        int gy = gy0 + HALO + ty;
        int gx = gx0 + HALO + tx;

        float center = s_ed[ty + 1][tx + 1];
        float res;
        if (gy == 0 || gy == H - 1 || gx == 0 || gx == W - 1) {
            res = center;  // reference only suppresses the [1:-1,1:-1] interior
        } else {
            float m = fmaxf(fmaxf(fmaxf(s_ed[ty    ][tx], s_ed[ty    ][tx + 1]),
                                  fmaxf(s_ed[ty    ][tx + 2], s_ed[ty + 1][tx])),
                            fmaxf(fmaxf(s_ed[ty + 1][tx + 2], s_ed[ty + 2][tx]),
                                  fmaxf(s_ed[ty + 2][tx + 1], s_ed[ty + 2][tx + 2])));
            res = (center < m) ? 0.0f : center;
        }
        out[out_base + (size_t)gy * W + gx] = res;
    }
}

extern "C" void kernel_launch(void* const* d_in, const int* in_sizes, int n_in,
                              void* d_out, int out_size)
{
    const float* img = (const float*)d_in[0];
    float* out = (float*)d_out;

    const int N = 16, H = 2048, W = 2048;

    dim3 block(32, 8, 1);
    dim3 grid(W / TS, H / TS, N);
    edge_detector_kernel<<<grid, block>>>(img, out, H, W);
}

// round 3
// speedup vs baseline: 1.9025x; 1.9025x over previous
#include <cuda_runtime.h>
#include <math.h>

#define W  2048
#define H  2048
#define NIMG 16

#define STRIP_OUT 120            // output columns per warp strip
#define NSTRIPS   18             // ceil(2048/120)
#define ROWT      64             // output rows per warp job
#define NROWT     32             // 2048/64
#define WARPS_PER_BLOCK 8
#define NJOBS (NIMG * NROWT * NSTRIPS)          // 9216
#define NBLOCKS (NJOBS / WARPS_PER_BLOCK)       // 1152

__device__ __forceinline__ float4 ld_row(const float* __restrict__ im,
                                         int y, int c0, bool colok)
{
    if (y < 0 || y >= H || !colok) return make_float4(0.f, 0.f, 0.f, 0.f);
    return *reinterpret_cast<const float4*>(im + (size_t)y * W + c0);
}

__global__ __launch_bounds__(256, 2)
void edge_kernel(const float* __restrict__ img, float* __restrict__ out)
{
    const int lane = threadIdx.x & 31;
    const int warp = threadIdx.x >> 5;
    const int job  = blockIdx.x * WARPS_PER_BLOCK + warp;

    const int strip = job % NSTRIPS;
    const int t     = job / NSTRIPS;
    const int rowt  = t % NROWT;
    const int n     = t / NROWT;

    const int cb = strip * STRIP_OUT - 4;   // loaded column base (mult of 4)
    const int c0 = cb + lane * 4;           // this lane's first column
    const int y0 = rowt * ROWT;

    const float* im = img + (size_t)n * H * W;
    float*       op = out + (size_t)n * H * W;

    // W % 4 == 0 and c0 % 4 == 0  =>  the whole float4 is in-image or fully out.
    const bool colok = (c0 >= 0) && (c0 < W);
    const bool storer = (lane >= 1) && (lane <= 30) && colok;

    // register rings (rows), 4 columns per lane
    float h0[4], h1[4], h2[4];
    float p0[4], p1[4], p2[4];
    float q0[4], q1[4], q2[4];
    float e0[4], e1[4], e2[4];
    float m0[4], m1[4], m2[4];
    float s1[4], s2[4];
    #pragma unroll
    for (int j = 0; j < 4; j++) {
        h0[j]=h1[j]=h2[j]=0.f; p0[j]=p1[j]=p2[j]=0.f; q0[j]=q1[j]=q2[j]=0.f;
        e0[j]=e1[j]=e2[j]=0.f; m0[j]=m1[j]=m2[j]=0.f; s1[j]=s2[j]=0.f;
    }

    // 1-deep prefetch of input rows
    float4 nx = ld_row(im, y0 - 3, c0, colok);

    for (int iy = 0; iy < ROWT + 6; iy++) {
        const int y = y0 - 3 + iy;
        float4 cur = nx;
        nx = ld_row(im, y + 1, c0, colok);     // prefetch next row

        // ---- h(y): horizontal [1,2,1] of input ----
        float inm1 = __shfl_up_sync(0xffffffffu, cur.w, 1);   // in[c0-1]
        float inp4 = __shfl_down_sync(0xffffffffu, cur.x, 1); // in[c0+4]
        #pragma unroll
        for (int j = 0; j < 4; j++) { h0[j] = h1[j]; h1[j] = h2[j]; }
        h2[0] = inm1  + 2.f*cur.x + cur.y;
        h2[1] = cur.x + 2.f*cur.y + cur.z;
        h2[2] = cur.y + 2.f*cur.z + cur.w;
        h2[3] = cur.z + 2.f*cur.w + inp4;

        if (iy >= 2) {
            // ---- sm(ys = y-1): vertical [1,2,1] of h, /16; zero outside image
            //      (reference zero-pads the SMOOTHED tensor for the Sobel conv)
            const int ys = y - 1;
            const bool smok = colok && (ys >= 0) && (ys < H);
            float sm[4];
            #pragma unroll
            for (int j = 0; j < 4; j++)
                sm[j] = smok ? (h0[j] + 2.f*h1[j] + h2[j]) * 0.0625f : 0.f;

            float smm1 = __shfl_up_sync(0xffffffffu, sm[3], 1);   // sm[c0-1]
            float smp4 = __shfl_down_sync(0xffffffffu, sm[0], 1); // sm[c0+4]

            // ---- p(ys) = sm(x+1)-sm(x-1),  q(ys) = sm(x-1)+2sm(x)+sm(x+1) ----
            #pragma unroll
            for (int j = 0; j < 4; j++) { p0[j]=p1[j]; p1[j]=p2[j]; q0[j]=q1[j]; q1[j]=q2[j]; }
            p2[0] = sm[1] - smm1;  q2[0] = smm1  + 2.f*sm[0] + sm[1];
            p2[1] = sm[2] - sm[0]; q2[1] = sm[0] + 2.f*sm[1] + sm[2];
            p2[2] = sm[3] - sm[1]; q2[2] = sm[1] + 2.f*sm[2] + sm[3];
            p2[3] = smp4  - sm[2]; q2[3] = sm[2] + 2.f*sm[3] + smp4;

            if (iy >= 4) {
                // ---- e(ye = y-2): gx = p0+2p1+p2 (vert [1,2,1]),
                //                   gy = q2-q0    (vert [-1,0,1]) ----
                #pragma unroll
                for (int j = 0; j < 4; j++) {
                    e0[j]=e1[j]; e1[j]=e2[j];
                    m0[j]=m1[j]; m1[j]=m2[j];
                    s1[j]=s2[j];
                }
                #pragma unroll
                for (int j = 0; j < 4; j++) {
                    float gx = p0[j] + 2.f*p1[j] + p2[j];
                    float gy = q2[j] - q0[j];
                    e2[j] = sqrtf(gx*gx + gy*gy);
                }
                float el = __shfl_up_sync(0xffffffffu, e2[3], 1);   // e[c0-1]
                float er = __shfl_down_sync(0xffffffffu, e2[0], 1); // e[c0+4]

                // row-max m (incl center) and side-max s (excl center)
                m2[0] = fmaxf(fmaxf(el,    e2[0]), e2[1]);  s2[0] = fmaxf(el,    e2[1]);
                m2[1] = fmaxf(fmaxf(e2[0], e2[1]), e2[2]);  s2[1] = fmaxf(e2[0], e2[2]);
                m2[2] = fmaxf(fmaxf(e2[1], e2[2]), e2[3]);  s2[2] = fmaxf(e2[1], e2[3]);
                m2[3] = fmaxf(fmaxf(e2[2], e2[3]), er);     s2[3] = fmaxf(e2[2], er);

                if (iy >= 6 && storer) {
                    // ---- NMS output at yo = y-3 ----
                    const int yo = y - 3;
                    const bool irow = (yo > 0) && (yo < H - 1);
                    float4 res;
                    float r[4];
                    #pragma unroll
                    for (int j = 0; j < 4; j++) {
                        const int col = c0 + j;
                        const float c = e1[j];
                        const float nm = fmaxf(fmaxf(m0[j], m2[j]), s1[j]);
                        const bool interior = irow && (col > 0) && (col < W - 1);
                        r[j] = (interior && c < nm) ? 0.f : c;
                    }
                    res.x = r[0]; res.y = r[1]; res.z = r[2]; res.w = r[3];
                    *reinterpret_cast<float4*>(op + (size_t)yo * W + c0) = res;
                }
            }
        }
    }
}

extern "C" void kernel_launch(void* const* d_in, const int* in_sizes, int n_in,
                              void* d_out, int out_size)
{
    const float* img = (const float*)d_in[0];
    float* out = (float*)d_out;
    edge_kernel<<<NBLOCKS, 256>>>(img, out);
}